// round 16
// baseline (speedup 1.0000x reference)
#include <cuda_runtime.h>
#include <cuda_bf16.h>
#include <mma.h>

using namespace nvcuda;
typedef __nv_bfloat16 bf;

// Problem constants (fixed by setup_inputs)
#define H 512
#define T_TREES 1024

#define GRID   296          // 2 blocks/SM, guaranteed co-resident (296 <= 2*148)
#define COMPB  256          // compute blocks (gemm grid 64 tiles x splitK 4)
#define POOLB  (GRID - COMPB)
#define POOL_ITEMS   131072 // 1024 trees x 128 float4 cols
#define POOL_HEAD    32768  // items done by the 40 pool blocks DURING the chain

// ---------------- device scratch (no allocs allowed) ----------------
__device__ bf g_WsT_h[H * H], g_WsT_l[H * H];
__device__ bf g_WzfT_h[H * H], g_WzfT_l[H * H];
__device__ bf g_N_h[H * H],  g_N_l[H * H];
__device__ bf g_N2_h[H * H], g_N2_l[H * H];
__device__ bf g_G_h[H * H],  g_G_l[H * H];
__device__ bf g_S_h[T_TREES * H], g_S_l[T_TREES * H];
__device__ float g_Nf[H * H];
__device__ float g_N2f[H * H];
__device__ float g_c[H];
__device__ float g_d[H];
__device__ float g_part1[4 * H * H];        // N partials
__device__ float g_part2[4 * H * H];        // N2 partials
__device__ float g_part3[4 * H * H];        // G partials
__device__ float g_partF[2 * T_TREES * H];  // final partials
__device__ unsigned long long g_bar[16];    // monotonic barrier counters

__device__ __forceinline__ void split2(float a, bf* h, bf* l) {
    bf hh = __float2bfloat16(a);
    *h = hh;
    *l = __float2bfloat16(a - __bfloat162float(hh));
}

// Monotonic-epoch grid barrier: counters never reset, so graph replays are safe.
__device__ __forceinline__ void gbar(int id, unsigned expected) {
    __syncthreads();
    if (threadIdx.x == 0) {
        __threadfence();
        unsigned long long my = atomicAdd(&g_bar[id], 1ULL) + 1ULL;
        unsigned long long target =
            ((my + (unsigned long long)expected - 1ULL) / expected) * expected;
        while (*((volatile unsigned long long*)&g_bar[id]) < target)
            __nanosleep(64);
    }
    __syncthreads();
}

// ---------------- one pooled column-sum item ----------------
__device__ __forceinline__ void pool_one(const float4* __restrict__ x4, int idx) {
    int t = idx >> 7, q = idx & 127;
    const float4* p = x4 + (size_t)t * 8192 + q;
    float4 s = make_float4(0.f, 0.f, 0.f, 0.f);
#pragma unroll 16
    for (int r = 0; r < 64; ++r) {
        float4 v = p[(size_t)r * 128];
        s.x += v.x; s.y += v.y; s.z += v.z; s.w += v.w;
    }
    int o = t * H + q * 4;
    split2(s.x, &g_S_h[o + 0], &g_S_l[o + 0]);
    split2(s.y, &g_S_h[o + 1], &g_S_l[o + 1]);
    split2(s.z, &g_S_h[o + 2], &g_S_l[o + 2]);
    split2(s.w, &g_S_h[o + 3], &g_S_l[o + 3]);
}

// ---------------- bf16x2-split wmma GEMM tile (proven R13/R14 math) ----------------
// 256 threads, 8 warps (2x4), 64x64 tile, BK=32 double-buffered, 3-pass hi/lo.
__device__ __forceinline__ void tile_gemm(
    const bf* __restrict__ Ah, const bf* __restrict__ Al,
    const bf* __restrict__ Bh, const bf* __restrict__ Bl,
    float* __restrict__ Cdst,
    int rb, int cb, int k0, int nk, char* s_raw)
{
    bf (*sA)[64][40] = reinterpret_cast<bf (*)[64][40]>(s_raw);          // [buf*2+hl]
    bf (*sB)[32][72] = reinterpret_cast<bf (*)[32][72]>(s_raw + 20480);

    const int tid = threadIdx.x;
    const int wid = tid >> 5;
    const int wr = (wid >> 2) * 32, wc = (wid & 3) * 16;

    const int ra = tid >> 2, ka = (tid & 3) * 8;     // A loader
    const int kb = tid >> 3, cq = (tid & 7) * 8;     // B loader

    const bf* pAh = Ah + (size_t)(rb + ra) * H + k0 + ka;
    const bf* pAl = Al + (size_t)(rb + ra) * H + k0 + ka;
    const bf* pBh = Bh + (size_t)(k0 + kb) * H + cb + cq;
    const bf* pBl = Bl + (size_t)(k0 + kb) * H + cb + cq;

    uint4 rAh = *(const uint4*)pAh;
    uint4 rAl = *(const uint4*)pAl;
    uint4 rBh = *(const uint4*)pBh;
    uint4 rBl = *(const uint4*)pBl;
    *(uint4*)&sA[0][ra][ka] = rAh;
    *(uint4*)&sA[1][ra][ka] = rAl;
    *(uint4*)&sB[0][kb][cq] = rBh;
    *(uint4*)&sB[1][kb][cq] = rBl;
    __syncthreads();

    wmma::fragment<wmma::accumulator, 16, 16, 16, float> acc[2];
    wmma::fill_fragment(acc[0], 0.f);
    wmma::fill_fragment(acc[1], 0.f);

    for (int kt = 0; kt < nk; ++kt) {
        int cur = kt & 1, nxt = cur ^ 1;
        if (kt + 1 < nk) {
            int off = (kt + 1) * 32;
            rAh = *(const uint4*)(pAh + off);
            rAl = *(const uint4*)(pAl + off);
            rBh = *(const uint4*)(pBh + (size_t)off * H);
            rBl = *(const uint4*)(pBl + (size_t)off * H);
        }
#pragma unroll
        for (int kk = 0; kk < 32; kk += 16) {
            wmma::fragment<wmma::matrix_a, 16, 16, 16, bf, wmma::row_major> fa;
            wmma::fragment<wmma::matrix_b, 16, 16, 16, bf, wmma::row_major> fbh, fbl;
            wmma::load_matrix_sync(fbh, &sB[cur * 2 + 0][kk][wc], 72);
            wmma::load_matrix_sync(fbl, &sB[cur * 2 + 1][kk][wc], 72);
#pragma unroll
            for (int i = 0; i < 2; ++i) {
                wmma::load_matrix_sync(fa, &sA[cur * 2 + 0][wr + i * 16][kk], 40);
                wmma::mma_sync(acc[i], fa, fbh, acc[i]);
                wmma::mma_sync(acc[i], fa, fbl, acc[i]);
            }
#pragma unroll
            for (int i = 0; i < 2; ++i) {
                wmma::load_matrix_sync(fa, &sA[cur * 2 + 1][wr + i * 16][kk], 40);
                wmma::mma_sync(acc[i], fa, fbh, acc[i]);
            }
        }
        if (kt + 1 < nk) {
            *(uint4*)&sA[nxt * 2 + 0][ra][ka] = rAh;
            *(uint4*)&sA[nxt * 2 + 1][ra][ka] = rAl;
            *(uint4*)&sB[nxt * 2 + 0][kb][cq] = rBh;
            *(uint4*)&sB[nxt * 2 + 1][kb][cq] = rBl;
        }
        __syncthreads();
    }

    // epilogue: stage accumulators (alias smem), then coalesced fp32 write
    float (*sC)[68] = reinterpret_cast<float (*)[68]>(s_raw);
#pragma unroll
    for (int i = 0; i < 2; ++i)
        wmma::store_matrix_sync(&sC[wr + i * 16][wc], acc[i], 68, wmma::mem_row_major);
    __syncthreads();
#pragma unroll
    for (int rep = 0; rep < 4; ++rep) {
        int e = rep * 256 + tid;
        int row = e >> 4, c4 = (e & 15) * 4;
        *(float4*)&Cdst[(size_t)(rb + row) * H + cb + c4] = *(float4*)&sC[row][c4];
    }
    __syncthreads();   // smem reusable by caller
}

// ---------------- combine 4 split-K partials, write fp32 (opt) + hi/lo ----------------
__device__ __forceinline__ void combine4(const float* __restrict__ part,
                                         float* __restrict__ dstF,
                                         bf* __restrict__ dstH, bf* __restrict__ dstL,
                                         int b)
{
    int i = b * 256 + threadIdx.x;   // 0..65535 float4 positions
    const float4* p = (const float4*)part;
    float4 r = p[i];
    float4 a = p[i + 65536], c = p[i + 131072], e = p[i + 196608];
    r.x += a.x + c.x + e.x;
    r.y += a.y + c.y + e.y;
    r.z += a.z + c.z + e.z;
    r.w += a.w + c.w + e.w;
    if (dstF) ((float4*)dstF)[i] = r;
    int o = i * 4;
    split2(r.x, dstH + o + 0, dstL + o + 0);
    split2(r.y, dstH + o + 1, dstL + o + 1);
    split2(r.z, dstH + o + 2, dstL + o + 2);
    split2(r.w, dstH + o + 3, dstL + o + 3);
}

// ---------------- the mega kernel ----------------
__global__ __launch_bounds__(256, 2)
void k_mega(const float4* __restrict__ x4, const float* __restrict__ Wz,
            const float* __restrict__ bzv, const float* __restrict__ Wzf,
            const float* __restrict__ bzf, float* __restrict__ out)
{
    __shared__ __align__(16) char s_raw[38912];
    const int b = blockIdx.x;
    const int tid = threadIdx.x;

    if (b < COMPB) {
        // ================= P0: prep (WsT, WzfT transposed+split; c) =================
        {
            float (*tile)[33] = reinterpret_cast<float (*)[33]>(s_raw);
            int tx = tid & 31, ty = tid >> 5;
            int bx = b & 15, by = b >> 4;
#pragma unroll
            for (int i = 0; i < 4; ++i) {
                int r = by * 32 + ty + i * 8;
                int c = bx * 32 + tx;
                tile[ty + i * 8][tx] =
                    Wz[0 * H * H + r * H + c] + Wz[1 * H * H + r * H + c] +
                    Wz[2 * H * H + r * H + c] + Wz[3 * H * H + r * H + c];
            }
            __syncthreads();
#pragma unroll
            for (int i = 0; i < 4; ++i) {
                int idx = (bx * 32 + ty + i * 8) * H + by * 32 + tx;
                split2(tile[tx][ty + i * 8], &g_WsT_h[idx], &g_WsT_l[idx]);
            }
            __syncthreads();
#pragma unroll
            for (int i = 0; i < 4; ++i)
                tile[ty + i * 8][tx] = Wzf[(by * 32 + ty + i * 8) * H + bx * 32 + tx];
            __syncthreads();
#pragma unroll
            for (int i = 0; i < 4; ++i) {
                int idx = (bx * 32 + ty + i * 8) * H + by * 32 + tx;
                split2(tile[tx][ty + i * 8], &g_WzfT_h[idx], &g_WzfT_l[idx]);
            }
            __syncthreads();
            if (b < 2) {   // c = 4 * (Wzf @ bsum + bzf)
                float* sb_ = reinterpret_cast<float*>(s_raw);
#pragma unroll
                for (int i = 0; i < 2; ++i) {
                    int hh = tid + i * 256;
                    sb_[hh] = bzv[hh] + bzv[H + hh] + bzv[2 * H + hh] + bzv[3 * H + hh];
                }
                __syncthreads();
                int j = b * 256 + tid;
                float acc = 0.f;
#pragma unroll 8
                for (int h = 0; h < H; ++h)
                    acc += Wzf[(size_t)j * H + h] * sb_[h];
                g_c[j] = 4.0f * (acc + bzf[j]);
            }
        }
        gbar(0, COMPB);

        const int gx = (b & 7) * 64, gy = ((b >> 3) & 7) * 64, gz = b >> 6; // splitK4

        // ================= N = WsT @ WzfT =================
        tile_gemm(g_WsT_h, g_WsT_l, g_WzfT_h, g_WzfT_l,
                  g_part1 + (size_t)gz * H * H, gx, gy, gz * 128, 4, s_raw);
        gbar(1, COMPB);
        combine4(g_part1, g_Nf, g_N_h, g_N_l, b);
        gbar(2, COMPB);

        // ================= N2 = N @ N =================
        tile_gemm(g_N_h, g_N_l, g_N_h, g_N_l,
                  g_part2 + (size_t)gz * H * H, gx, gy, gz * 128, 4, s_raw);
        gbar(3, COMPB);
        combine4(g_part2, g_N2f, g_N2_h, g_N2_l, b);
        gbar(4, COMPB);

        // ================= G = N2 @ N =================
        tile_gemm(g_N2_h, g_N2_l, g_N_h, g_N_l,
                  g_part3 + (size_t)gz * H * H, gx, gy, gz * 128, 4, s_raw);
        gbar(5, COMPB);
        combine4(g_part3, nullptr, g_G_h, g_G_l, b);

        // d = 16 M^2 c + 4 M c + c   (blocks 0,1)
        if (b < 2) {
            int j = b * 256 + tid;
            float acc = 0.f;
#pragma unroll 8
            for (int h = 0; h < H; ++h) {
                float ch = g_c[h];
                acc += ch * (16.0f * g_N2f[h * H + j] + 4.0f * g_Nf[h * H + j]);
            }
            g_d[j] = acc + g_c[j];
        }
    } else {
        // ========= pool blocks: stream the HEAD of x during the chain =========
        for (int idx = (b - COMPB) * 256 + tid; idx < POOL_HEAD; idx += POOLB * 256)
            pool_one(x4, idx);
    }

    gbar(6, GRID);   // chain done (G, d ready); head pool done

    // ========= pool TAIL: ALL blocks cooperate at full-chip bandwidth =========
    for (int idx = POOL_HEAD + b * 256 + tid; idx < POOL_ITEMS; idx += GRID * 256)
        pool_one(x4, idx);

    gbar(7, GRID);   // S complete

    // ================= final: out_partials = S @ G  (splitK 2) =================
    if (b < COMPB) {
        int t = b & 127;
        int rb = (t & 15) * 64, cb = ((t >> 4) & 7) * 64, z = b >> 7;
        tile_gemm(g_S_h, g_S_l, g_G_h, g_G_l,
                  g_partF + (size_t)z * T_TREES * H, rb, cb, z * 256, 8, s_raw);
    }
    gbar(8, GRID);

    // ================= combineF: out = partF0 + partF1 + d =================
    for (int i = b * 256 + tid; i < T_TREES * H / 4; i += GRID * 256) {
        const float4* p = (const float4*)g_partF;
        float4 r = p[i], v = p[i + 131072];
        float4 dv = ((const float4*)g_d)[i & 127];
        r.x += v.x + dv.x;
        r.y += v.y + dv.y;
        r.z += v.z + dv.z;
        r.w += v.w + dv.w;
        ((float4*)out)[i] = r;
    }
}

// ---------------- launch: ONE kernel, no streams, no events ----------------
extern "C" void kernel_launch(void* const* d_in, const int* in_sizes, int n_in,
                              void* d_out, int out_size) {
    const float* x   = (const float*)d_in[0];
    const float* Wz  = (const float*)d_in[1];
    const float* bz  = (const float*)d_in[2];
    const float* Wzf = (const float*)d_in[3];
    const float* bzf = (const float*)d_in[4];
    float* out = (float*)d_out;

    k_mega<<<GRID, 256>>>((const float4*)x, Wz, bz, Wzf, bzf, out);
}

// round 17
// speedup vs baseline: 1.0519x; 1.0519x over previous
#include <cuda_runtime.h>
#include <cuda_bf16.h>
#include <mma.h>

using namespace nvcuda;
typedef __nv_bfloat16 bf;

// Problem constants (fixed by setup_inputs)
#define H 512
#define T_TREES 1024

#define GRID   296          // 2 blocks/SM, guaranteed co-resident (296 <= 2*148)
#define COMPB  256          // compute blocks (gemm grid 64 tiles x splitK 4)
#define POOLB  (GRID - COMPB)
#define POOL_ITEMS   131072 // 1024 trees x 128 float4 cols
#define POOL_HEAD    65536  // items done by the 40 pool blocks DURING the chain

// ---------------- device scratch (no allocs allowed) ----------------
__device__ bf g_WsT_h[H * H], g_WsT_l[H * H];
__device__ bf g_WzfT_h[H * H], g_WzfT_l[H * H];
__device__ bf g_N_h[H * H],  g_N_l[H * H];
__device__ bf g_N2_h[H * H], g_N2_l[H * H];
__device__ bf g_G_h[H * H],  g_G_l[H * H];
__device__ bf g_S_h[T_TREES * H], g_S_l[T_TREES * H];
__device__ float g_Nf[H * H];
__device__ float g_N2f[H * H];
__device__ float g_c[H];
__device__ float g_d[H];
__device__ float g_part1[4 * H * H];        // N partials
__device__ float g_part2[4 * H * H];        // N2 partials
__device__ float g_part3[4 * H * H];        // G partials
__device__ float g_partF[2 * T_TREES * H];  // final partials
__device__ unsigned long long g_bar[16];    // monotonic barrier counters

__device__ __forceinline__ void split2(float a, bf* h, bf* l) {
    bf hh = __float2bfloat16(a);
    *h = hh;
    *l = __float2bfloat16(a - __bfloat162float(hh));
}

// Monotonic-epoch grid barrier: counters never reset, so graph replays are safe.
__device__ __forceinline__ void gbar(int id, unsigned expected) {
    __syncthreads();
    if (threadIdx.x == 0) {
        __threadfence();
        unsigned long long my = atomicAdd(&g_bar[id], 1ULL) + 1ULL;
        unsigned long long target =
            ((my + (unsigned long long)expected - 1ULL) / expected) * expected;
        while (*((volatile unsigned long long*)&g_bar[id]) < target)
            __nanosleep(64);
    }
    __syncthreads();
}

// ---------------- one pooled column-sum item, explicit 8-way MLP ----------------
__device__ __forceinline__ void pool_one(const float4* __restrict__ x4, int idx) {
    int t = idx >> 7, q = idx & 127;
    const float4* p = x4 + (size_t)t * 8192 + q;
    float4 s0 = make_float4(0.f, 0.f, 0.f, 0.f);
    float4 s1 = s0, s2 = s0, s3 = s0;
#pragma unroll
    for (int r = 0; r < 64; r += 8) {
        // 8 independent loads issued back-to-back (front-batched by ptxas),
        // accumulated into 4 rotating accumulators (short FADD chains).
        float4 v0 = p[(r + 0) * 128];
        float4 v1 = p[(r + 1) * 128];
        float4 v2 = p[(r + 2) * 128];
        float4 v3 = p[(r + 3) * 128];
        float4 v4 = p[(r + 4) * 128];
        float4 v5 = p[(r + 5) * 128];
        float4 v6 = p[(r + 6) * 128];
        float4 v7 = p[(r + 7) * 128];
        s0.x += v0.x; s0.y += v0.y; s0.z += v0.z; s0.w += v0.w;
        s1.x += v1.x; s1.y += v1.y; s1.z += v1.z; s1.w += v1.w;
        s2.x += v2.x; s2.y += v2.y; s2.z += v2.z; s2.w += v2.w;
        s3.x += v3.x; s3.y += v3.y; s3.z += v3.z; s3.w += v3.w;
        s0.x += v4.x; s0.y += v4.y; s0.z += v4.z; s0.w += v4.w;
        s1.x += v5.x; s1.y += v5.y; s1.z += v5.z; s1.w += v5.w;
        s2.x += v6.x; s2.y += v6.y; s2.z += v6.z; s2.w += v6.w;
        s3.x += v7.x; s3.y += v7.y; s3.z += v7.z; s3.w += v7.w;
    }
    float4 s;
    s.x = (s0.x + s1.x) + (s2.x + s3.x);
    s.y = (s0.y + s1.y) + (s2.y + s3.y);
    s.z = (s0.z + s1.z) + (s2.z + s3.z);
    s.w = (s0.w + s1.w) + (s2.w + s3.w);
    int o = t * H + q * 4;
    split2(s.x, &g_S_h[o + 0], &g_S_l[o + 0]);
    split2(s.y, &g_S_h[o + 1], &g_S_l[o + 1]);
    split2(s.z, &g_S_h[o + 2], &g_S_l[o + 2]);
    split2(s.w, &g_S_h[o + 3], &g_S_l[o + 3]);
}

// ---------------- bf16x2-split wmma GEMM tile (proven R13/R14 math) ----------------
// 256 threads, 8 warps (2x4), 64x64 tile, BK=32 double-buffered, 3-pass hi/lo.
__device__ __forceinline__ void tile_gemm(
    const bf* __restrict__ Ah, const bf* __restrict__ Al,
    const bf* __restrict__ Bh, const bf* __restrict__ Bl,
    float* __restrict__ Cdst,
    int rb, int cb, int k0, int nk, char* s_raw)
{
    bf (*sA)[64][40] = reinterpret_cast<bf (*)[64][40]>(s_raw);          // [buf*2+hl]
    bf (*sB)[32][72] = reinterpret_cast<bf (*)[32][72]>(s_raw + 20480);

    const int tid = threadIdx.x;
    const int wid = tid >> 5;
    const int wr = (wid >> 2) * 32, wc = (wid & 3) * 16;

    const int ra = tid >> 2, ka = (tid & 3) * 8;     // A loader
    const int kb = tid >> 3, cq = (tid & 7) * 8;     // B loader

    const bf* pAh = Ah + (size_t)(rb + ra) * H + k0 + ka;
    const bf* pAl = Al + (size_t)(rb + ra) * H + k0 + ka;
    const bf* pBh = Bh + (size_t)(k0 + kb) * H + cb + cq;
    const bf* pBl = Bl + (size_t)(k0 + kb) * H + cb + cq;

    uint4 rAh = *(const uint4*)pAh;
    uint4 rAl = *(const uint4*)pAl;
    uint4 rBh = *(const uint4*)pBh;
    uint4 rBl = *(const uint4*)pBl;
    *(uint4*)&sA[0][ra][ka] = rAh;
    *(uint4*)&sA[1][ra][ka] = rAl;
    *(uint4*)&sB[0][kb][cq] = rBh;
    *(uint4*)&sB[1][kb][cq] = rBl;
    __syncthreads();

    wmma::fragment<wmma::accumulator, 16, 16, 16, float> acc[2];
    wmma::fill_fragment(acc[0], 0.f);
    wmma::fill_fragment(acc[1], 0.f);

    for (int kt = 0; kt < nk; ++kt) {
        int cur = kt & 1, nxt = cur ^ 1;
        if (kt + 1 < nk) {
            int off = (kt + 1) * 32;
            rAh = *(const uint4*)(pAh + off);
            rAl = *(const uint4*)(pAl + off);
            rBh = *(const uint4*)(pBh + (size_t)off * H);
            rBl = *(const uint4*)(pBl + (size_t)off * H);
        }
#pragma unroll
        for (int kk = 0; kk < 32; kk += 16) {
            wmma::fragment<wmma::matrix_a, 16, 16, 16, bf, wmma::row_major> fa;
            wmma::fragment<wmma::matrix_b, 16, 16, 16, bf, wmma::row_major> fbh, fbl;
            wmma::load_matrix_sync(fbh, &sB[cur * 2 + 0][kk][wc], 72);
            wmma::load_matrix_sync(fbl, &sB[cur * 2 + 1][kk][wc], 72);
#pragma unroll
            for (int i = 0; i < 2; ++i) {
                wmma::load_matrix_sync(fa, &sA[cur * 2 + 0][wr + i * 16][kk], 40);
                wmma::mma_sync(acc[i], fa, fbh, acc[i]);
                wmma::mma_sync(acc[i], fa, fbl, acc[i]);
            }
#pragma unroll
            for (int i = 0; i < 2; ++i) {
                wmma::load_matrix_sync(fa, &sA[cur * 2 + 1][wr + i * 16][kk], 40);
                wmma::mma_sync(acc[i], fa, fbh, acc[i]);
            }
        }
        if (kt + 1 < nk) {
            *(uint4*)&sA[nxt * 2 + 0][ra][ka] = rAh;
            *(uint4*)&sA[nxt * 2 + 1][ra][ka] = rAl;
            *(uint4*)&sB[nxt * 2 + 0][kb][cq] = rBh;
            *(uint4*)&sB[nxt * 2 + 1][kb][cq] = rBl;
        }
        __syncthreads();
    }

    // epilogue: stage accumulators (alias smem), then coalesced fp32 write
    float (*sC)[68] = reinterpret_cast<float (*)[68]>(s_raw);
#pragma unroll
    for (int i = 0; i < 2; ++i)
        wmma::store_matrix_sync(&sC[wr + i * 16][wc], acc[i], 68, wmma::mem_row_major);
    __syncthreads();
#pragma unroll
    for (int rep = 0; rep < 4; ++rep) {
        int e = rep * 256 + tid;
        int row = e >> 4, c4 = (e & 15) * 4;
        *(float4*)&Cdst[(size_t)(rb + row) * H + cb + c4] = *(float4*)&sC[row][c4];
    }
    __syncthreads();   // smem reusable by caller
}

// ---------------- combine 4 split-K partials, write fp32 (opt) + hi/lo ----------------
__device__ __forceinline__ void combine4(const float* __restrict__ part,
                                         float* __restrict__ dstF,
                                         bf* __restrict__ dstH, bf* __restrict__ dstL,
                                         int b)
{
    int i = b * 256 + threadIdx.x;   // 0..65535 float4 positions
    const float4* p = (const float4*)part;
    float4 r = p[i];
    float4 a = p[i + 65536], c = p[i + 131072], e = p[i + 196608];
    r.x += a.x + c.x + e.x;
    r.y += a.y + c.y + e.y;
    r.z += a.z + c.z + e.z;
    r.w += a.w + c.w + e.w;
    if (dstF) ((float4*)dstF)[i] = r;
    int o = i * 4;
    split2(r.x, dstH + o + 0, dstL + o + 0);
    split2(r.y, dstH + o + 1, dstL + o + 1);
    split2(r.z, dstH + o + 2, dstL + o + 2);
    split2(r.w, dstH + o + 3, dstL + o + 3);
}

// ---------------- the mega kernel ----------------
__global__ __launch_bounds__(256, 2)
void k_mega(const float4* __restrict__ x4, const float* __restrict__ Wz,
            const float* __restrict__ bzv, const float* __restrict__ Wzf,
            const float* __restrict__ bzf, float* __restrict__ out)
{
    __shared__ __align__(16) char s_raw[38912];
    const int b = blockIdx.x;
    const int tid = threadIdx.x;

    if (b < COMPB) {
        // ================= P0: prep (WsT, WzfT transposed+split; c) =================
        {
            float (*tile)[33] = reinterpret_cast<float (*)[33]>(s_raw);
            int tx = tid & 31, ty = tid >> 5;
            int bx = b & 15, by = b >> 4;
#pragma unroll
            for (int i = 0; i < 4; ++i) {
                int r = by * 32 + ty + i * 8;
                int c = bx * 32 + tx;
                tile[ty + i * 8][tx] =
                    Wz[0 * H * H + r * H + c] + Wz[1 * H * H + r * H + c] +
                    Wz[2 * H * H + r * H + c] + Wz[3 * H * H + r * H + c];
            }
            __syncthreads();
#pragma unroll
            for (int i = 0; i < 4; ++i) {
                int idx = (bx * 32 + ty + i * 8) * H + by * 32 + tx;
                split2(tile[tx][ty + i * 8], &g_WsT_h[idx], &g_WsT_l[idx]);
            }
            __syncthreads();
#pragma unroll
            for (int i = 0; i < 4; ++i)
                tile[ty + i * 8][tx] = Wzf[(by * 32 + ty + i * 8) * H + bx * 32 + tx];
            __syncthreads();
#pragma unroll
            for (int i = 0; i < 4; ++i) {
                int idx = (bx * 32 + ty + i * 8) * H + by * 32 + tx;
                split2(tile[tx][ty + i * 8], &g_WzfT_h[idx], &g_WzfT_l[idx]);
            }
            __syncthreads();
            if (b < 2) {   // c = 4 * (Wzf @ bsum + bzf)
                float* sb_ = reinterpret_cast<float*>(s_raw);
#pragma unroll
                for (int i = 0; i < 2; ++i) {
                    int hh = tid + i * 256;
                    sb_[hh] = bzv[hh] + bzv[H + hh] + bzv[2 * H + hh] + bzv[3 * H + hh];
                }
                __syncthreads();
                int j = b * 256 + tid;
                float acc = 0.f;
#pragma unroll 8
                for (int h = 0; h < H; ++h)
                    acc += Wzf[(size_t)j * H + h] * sb_[h];
                g_c[j] = 4.0f * (acc + bzf[j]);
            }
        }
        gbar(0, COMPB);

        const int gx = (b & 7) * 64, gy = ((b >> 3) & 7) * 64, gz = b >> 6; // splitK4

        // ================= N = WsT @ WzfT =================
        tile_gemm(g_WsT_h, g_WsT_l, g_WzfT_h, g_WzfT_l,
                  g_part1 + (size_t)gz * H * H, gx, gy, gz * 128, 4, s_raw);
        gbar(1, COMPB);
        combine4(g_part1, g_Nf, g_N_h, g_N_l, b);
        gbar(2, COMPB);

        // ================= N2 = N @ N =================
        tile_gemm(g_N_h, g_N_l, g_N_h, g_N_l,
                  g_part2 + (size_t)gz * H * H, gx, gy, gz * 128, 4, s_raw);
        gbar(3, COMPB);
        combine4(g_part2, g_N2f, g_N2_h, g_N2_l, b);
        gbar(4, COMPB);

        // ================= G = N2 @ N =================
        tile_gemm(g_N2_h, g_N2_l, g_N_h, g_N_l,
                  g_part3 + (size_t)gz * H * H, gx, gy, gz * 128, 4, s_raw);
        gbar(5, COMPB);
        combine4(g_part3, nullptr, g_G_h, g_G_l, b);

        // d = 16 M^2 c + 4 M c + c   (blocks 0,1)
        if (b < 2) {
            int j = b * 256 + tid;
            float acc = 0.f;
#pragma unroll 8
            for (int h = 0; h < H; ++h) {
                float ch = g_c[h];
                acc += ch * (16.0f * g_N2f[h * H + j] + 4.0f * g_Nf[h * H + j]);
            }
            g_d[j] = acc + g_c[j];
        }
    } else {
        // ========= pool blocks: stream the HEAD of x during the chain =========
        for (int idx = (b - COMPB) * 256 + tid; idx < POOL_HEAD; idx += POOLB * 256)
            pool_one(x4, idx);
    }

    gbar(6, GRID);   // chain done (G, d ready); head pool done

    // ========= pool TAIL: ALL blocks cooperate at full-chip bandwidth =========
    for (int idx = POOL_HEAD + b * 256 + tid; idx < POOL_ITEMS; idx += GRID * 256)
        pool_one(x4, idx);

    gbar(7, GRID);   // S complete

    // ================= final: out_partials = S @ G  (splitK 2) =================
    if (b < COMPB) {
        int t = b & 127;
        int rb = (t & 15) * 64, cb = ((t >> 4) & 7) * 64, z = b >> 7;
        tile_gemm(g_S_h, g_S_l, g_G_h, g_G_l,
                  g_partF + (size_t)z * T_TREES * H, rb, cb, z * 256, 8, s_raw);
    }
    gbar(8, GRID);

    // ================= combineF: out = partF0 + partF1 + d =================
    for (int i = b * 256 + tid; i < T_TREES * H / 4; i += GRID * 256) {
        const float4* p = (const float4*)g_partF;
        float4 r = p[i], v = p[i + 131072];
        float4 dv = ((const float4*)g_d)[i & 127];
        r.x += v.x + dv.x;
        r.y += v.y + dv.y;
        r.z += v.z + dv.z;
        r.w += v.w + dv.w;
        ((float4*)out)[i] = r;
    }
}

// ---------------- launch: ONE kernel, no streams, no events ----------------
extern "C" void kernel_launch(void* const* d_in, const int* in_sizes, int n_in,
                              void* d_out, int out_size) {
    const float* x   = (const float*)d_in[0];
    const float* Wz  = (const float*)d_in[1];
    const float* bz  = (const float*)d_in[2];
    const float* Wzf = (const float*)d_in[3];
    const float* bzf = (const float*)d_in[4];
    float* out = (float*)d_out;

    k_mega<<<GRID, 256>>>((const float4*)x, Wz, bz, Wzf, bzf, out);
}